// round 2
// baseline (speedup 1.0000x reference)
#include <cuda_runtime.h>
#include <cstdint>

// TTAggregator: out[n,:] = U_outputᵀ · ris9, where
//   ris0[c]   = Σ_b U0[b,c] h0[b]
//   ris_d[c]  = Σ_{a,b} U_rest[d-1][a][b][c] ris_{d-1}[a] h_d[b]   (d = 1..9)
// neighbour_states: (N, 10, 16) f32; U0: (16,16); U_rest: (9,16,16,16); U_output: (16,16)

static constexpr int NROWS = 1000000;
static constexpr int DEG   = 10;
static constexpr int TPB   = 512;

// shared layout (floats):
//   [0, 36864)             U_rest
//   [36864, 37120)         U0
//   [37120, 37376)         U_output
//   [37376, 37376+512*17)  per-thread ris scratch (stride 17 -> conflict-free)
static constexpr int SM_U0     = 9 * 4096;
static constexpr int SM_UO     = SM_U0 + 256;
static constexpr int SM_RIS    = SM_UO + 256;
static constexpr int SM_FLOATS = SM_RIS + TPB * 17;
static constexpr int SMEM_BYTES = SM_FLOATS * 4;   // 184320 B

// ---- packed f32x2 helpers (Blackwell FFMA2 path) ----
__device__ __forceinline__ unsigned long long f2_pack(float x, float y) {
    unsigned long long r;
    asm("mov.b64 %0, {%1, %2};" : "=l"(r) : "f"(x), "f"(y));
    return r;
}
__device__ __forceinline__ void f2_unpack(unsigned long long v, float& x, float& y) {
    asm("mov.b64 {%0, %1}, %2;" : "=f"(x), "=f"(y) : "l"(v));
}
__device__ __forceinline__ unsigned long long f2_mul(unsigned long long a, unsigned long long b) {
    unsigned long long d;
    asm("mul.rn.f32x2 %0, %1, %2;" : "=l"(d) : "l"(a), "l"(b));
    return d;
}
__device__ __forceinline__ unsigned long long f2_fma(unsigned long long a, unsigned long long b,
                                                     unsigned long long c) {
    unsigned long long d;
    asm("fma.rn.f32x2 %0, %1, %2, %3;" : "=l"(d) : "l"(a), "l"(b), "l"(c));
    return d;
}

__global__ __launch_bounds__(TPB, 1)
void tt_agg_kernel(const float* __restrict__ ns,
                   const float* __restrict__ U0,
                   const float* __restrict__ Ur,
                   const float* __restrict__ Uo,
                   float* __restrict__ out)
{
    extern __shared__ float s[];
    float* sUr  = s;
    float* sU0  = s + SM_U0;
    float* sUo  = s + SM_UO;
    float* sRis = s + SM_RIS;

    // Stage all U tensors into shared (broadcast-read later).
    for (int i = threadIdx.x; i < 9 * 4096; i += TPB) sUr[i] = Ur[i];
    for (int i = threadIdx.x; i < 256; i += TPB) { sU0[i] = U0[i]; sUo[i] = Uo[i]; }
    __syncthreads();

    const long long row = (long long)blockIdx.x * TPB + threadIdx.x;
    if (row >= NROWS) return;

    const float* base = ns + (size_t)row * (DEG * 16);
    float* myris = sRis + threadIdx.x * 17;

    // ---- h0 load + ris0 = U0^T h0 ----
    float h[16];
    #pragma unroll
    for (int g = 0; g < 4; g++) {
        float4 v = *reinterpret_cast<const float4*>(base + g * 4);
        h[4*g+0] = v.x; h[4*g+1] = v.y; h[4*g+2] = v.z; h[4*g+3] = v.w;
    }
    float ris[16];
    #pragma unroll
    for (int c = 0; c < 16; c++) ris[c] = 0.f;
    #pragma unroll
    for (int b = 0; b < 16; b++) {
        float hb = h[b];
        #pragma unroll
        for (int c = 0; c < 16; c++)
            ris[c] = fmaf(sU0[b * 16 + c], hb, ris[c]);
    }

    // ---- 9 TT steps ----
    #pragma unroll 1
    for (int d = 1; d < DEG; d++) {
        // load h_d, pre-pack as {h,h} pairs for f32x2
        unsigned long long hh[16];
        #pragma unroll
        for (int g = 0; g < 4; g++) {
            float4 v = *reinterpret_cast<const float4*>(base + d * 16 + g * 4);
            hh[4*g+0] = f2_pack(v.x, v.x);
            hh[4*g+1] = f2_pack(v.y, v.y);
            hh[4*g+2] = f2_pack(v.z, v.z);
            hh[4*g+3] = f2_pack(v.w, v.w);
        }

        // spill ris to per-thread shared so the a-loop can stay rolled
        // (keeps SASS body small + avoids dynamic register indexing)
        #pragma unroll
        for (int c = 0; c < 16; c++) myris[c] = ris[c];

        unsigned long long acc[8];
        #pragma unroll
        for (int i = 0; i < 8; i++) acc[i] = 0ull;

        const float* Ud = sUr + (d - 1) * 4096;

        #pragma unroll 1
        for (int a = 0; a < 16; a++) {
            float ra = myris[a];
            unsigned long long rr = f2_pack(ra, ra);
            #pragma unroll
            for (int b = 0; b < 16; b++) {
                unsigned long long pp = f2_mul(rr, hh[b]);   // {ris[a]*h[b], same}
                const ulonglong2* u2 =
                    reinterpret_cast<const ulonglong2*>(Ud + (a * 16 + b) * 16);
                #pragma unroll
                for (int j = 0; j < 4; j++) {
                    ulonglong2 q = u2[j];                    // LDS.128 broadcast
                    acc[2*j + 0] = f2_fma(q.x, pp, acc[2*j + 0]);
                    acc[2*j + 1] = f2_fma(q.y, pp, acc[2*j + 1]);
                }
            }
        }
        #pragma unroll
        for (int i = 0; i < 8; i++) f2_unpack(acc[i], ris[2*i], ris[2*i+1]);
    }

    // ---- output projection: out[c] = Σ_a U_output[a,c] ris[a] ----
    float o[16];
    #pragma unroll
    for (int c = 0; c < 16; c++) o[c] = 0.f;
    #pragma unroll
    for (int a = 0; a < 16; a++) {
        float ra = ris[a];
        #pragma unroll
        for (int c = 0; c < 16; c++)
            o[c] = fmaf(sUo[a * 16 + c], ra, o[c]);
    }
    float4* op = reinterpret_cast<float4*>(out + (size_t)row * 16);
    #pragma unroll
    for (int g = 0; g < 4; g++)
        op[g] = make_float4(o[4*g+0], o[4*g+1], o[4*g+2], o[4*g+3]);
}

extern "C" void kernel_launch(void* const* d_in, const int* in_sizes, int n_in,
                              void* d_out, int out_size)
{
    const float* ns = (const float*)d_in[0];
    const float* U0 = (const float*)d_in[1];
    const float* Ur = (const float*)d_in[2];
    const float* Uo = (const float*)d_in[3];
    float* out = (float*)d_out;

    cudaFuncSetAttribute(tt_agg_kernel,
                         cudaFuncAttributeMaxDynamicSharedMemorySize, SMEM_BYTES);

    int grid = (NROWS + TPB - 1) / TPB;
    tt_agg_kernel<<<grid, TPB, SMEM_BYTES>>>(ns, U0, Ur, Uo, out);
}

// round 3
// speedup vs baseline: 1.2574x; 1.2574x over previous
#include <cuda_runtime.h>
#include <cstdint>

// TTAggregator: out[n,:] = U_outputᵀ · ris9, where
//   ris0[c]   = Σ_b U0[b,c] h0[b]
//   ris_d[c]  = Σ_{a,b} U_rest[d-1][a][b][c] ris_{d-1}[a] h_d[b]   (d = 1..9)
// neighbour_states: (N, 10, 16) f32; U0: (16,16); U_rest: (9,16,16,16); U_output: (16,16)
//
// R3: 2 rows per thread. The U-tile LDS.128 broadcasts (the R2 bottleneck at
// 95% L1 pipe) are amortized over 2 rows, halving shared traffic per row and
// rebalancing against the fma pipe.

static constexpr int NROWS = 1000000;
static constexpr int DEG   = 10;
static constexpr int TPB   = 384;
static constexpr int RPT   = 2;                    // rows per thread
static constexpr int ROWS_PER_BLK = TPB * RPT;     // 768

// shared layout (floats):
//   [0, 36864)               U_rest
//   [36864, 37120)           U0
//   [37120, 37376)           U_output
//   [37376, ...)             per-thread ris scratch, RPT arrays, stride 17
static constexpr int SM_U0     = 9 * 4096;
static constexpr int SM_UO     = SM_U0 + 256;
static constexpr int SM_RIS    = SM_UO + 256;
static constexpr int SM_FLOATS = SM_RIS + TPB * RPT * 17;
static constexpr int SMEM_BYTES = SM_FLOATS * 4;   // 201728 B

// ---- packed f32x2 helpers (Blackwell FFMA2 path) ----
__device__ __forceinline__ unsigned long long f2_pack(float x, float y) {
    unsigned long long r;
    asm("mov.b64 %0, {%1, %2};" : "=l"(r) : "f"(x), "f"(y));
    return r;
}
__device__ __forceinline__ void f2_unpack(unsigned long long v, float& x, float& y) {
    asm("mov.b64 {%0, %1}, %2;" : "=f"(x), "=f"(y) : "l"(v));
}
__device__ __forceinline__ unsigned long long f2_mul(unsigned long long a, unsigned long long b) {
    unsigned long long d;
    asm("mul.rn.f32x2 %0, %1, %2;" : "=l"(d) : "l"(a), "l"(b));
    return d;
}
__device__ __forceinline__ unsigned long long f2_fma(unsigned long long a, unsigned long long b,
                                                     unsigned long long c) {
    unsigned long long d;
    asm("fma.rn.f32x2 %0, %1, %2, %3;" : "=l"(d) : "l"(a), "l"(b), "l"(c));
    return d;
}

__global__ __launch_bounds__(TPB, 1)
void tt_agg_kernel(const float* __restrict__ ns,
                   const float* __restrict__ U0,
                   const float* __restrict__ Ur,
                   const float* __restrict__ Uo,
                   float* __restrict__ out)
{
    extern __shared__ float s[];
    float* sUr  = s;
    float* sU0  = s + SM_U0;
    float* sUo  = s + SM_UO;
    float* sRis = s + SM_RIS;

    // Stage all U tensors into shared (broadcast-read later).
    for (int i = threadIdx.x; i < 9 * 4096; i += TPB) sUr[i] = Ur[i];
    for (int i = threadIdx.x; i < 256; i += TPB) { sU0[i] = U0[i]; sUo[i] = Uo[i]; }
    __syncthreads();

    const long long blkbase = (long long)blockIdx.x * ROWS_PER_BLK;
    long long rown[RPT];
    bool active[RPT];
    const float* base[RPT];
    #pragma unroll
    for (int r = 0; r < RPT; r++) {
        rown[r]   = blkbase + threadIdx.x + r * TPB;
        active[r] = rown[r] < NROWS;
        // inactive rows compute on row 0 (harmless), store is predicated off
        base[r]   = ns + (size_t)(active[r] ? rown[r] : 0) * (DEG * 16);
    }
    float* myris[RPT];
    #pragma unroll
    for (int r = 0; r < RPT; r++)
        myris[r] = sRis + (threadIdx.x * RPT + r) * 17;

    // ---- h0 load + ris0 = U0^T h0 (per row) ----
    float ris[RPT][16];
    #pragma unroll
    for (int r = 0; r < RPT; r++) {
        float h[16];
        #pragma unroll
        for (int g = 0; g < 4; g++) {
            float4 v = *reinterpret_cast<const float4*>(base[r] + g * 4);
            h[4*g+0] = v.x; h[4*g+1] = v.y; h[4*g+2] = v.z; h[4*g+3] = v.w;
        }
        #pragma unroll
        for (int c = 0; c < 16; c++) ris[r][c] = 0.f;
        #pragma unroll
        for (int b = 0; b < 16; b++) {
            float hb = h[b];
            #pragma unroll
            for (int c = 0; c < 16; c++)
                ris[r][c] = fmaf(sU0[b * 16 + c], hb, ris[r][c]);
        }
    }

    // ---- 9 TT steps ----
    #pragma unroll 1
    for (int d = 1; d < DEG; d++) {
        // load h_d for each row, pre-pack as {h,h} pairs for f32x2
        unsigned long long hh[RPT][16];
        #pragma unroll
        for (int r = 0; r < RPT; r++) {
            #pragma unroll
            for (int g = 0; g < 4; g++) {
                float4 v = *reinterpret_cast<const float4*>(base[r] + d * 16 + g * 4);
                hh[r][4*g+0] = f2_pack(v.x, v.x);
                hh[r][4*g+1] = f2_pack(v.y, v.y);
                hh[r][4*g+2] = f2_pack(v.z, v.z);
                hh[r][4*g+3] = f2_pack(v.w, v.w);
            }
        }

        // spill ris to per-thread shared so the a-loop can stay rolled
        #pragma unroll
        for (int r = 0; r < RPT; r++)
            #pragma unroll
            for (int c = 0; c < 16; c++) myris[r][c] = ris[r][c];

        unsigned long long acc[RPT][8];
        #pragma unroll
        for (int r = 0; r < RPT; r++)
            #pragma unroll
            for (int i = 0; i < 8; i++) acc[r][i] = 0ull;

        const float* Ud = sUr + (d - 1) * 4096;

        #pragma unroll 1
        for (int a = 0; a < 16; a++) {
            unsigned long long rr[RPT];
            #pragma unroll
            for (int r = 0; r < RPT; r++) {
                float ra = myris[r][a];
                rr[r] = f2_pack(ra, ra);
            }
            #pragma unroll
            for (int b = 0; b < 16; b++) {
                unsigned long long pp[RPT];
                #pragma unroll
                for (int r = 0; r < RPT; r++)
                    pp[r] = f2_mul(rr[r], hh[r][b]);   // {ris[a]*h[b], same}

                const ulonglong2* u2 =
                    reinterpret_cast<const ulonglong2*>(Ud + (a * 16 + b) * 16);
                #pragma unroll
                for (int j = 0; j < 4; j++) {
                    ulonglong2 q = u2[j];              // LDS.128 broadcast, shared by RPT rows
                    #pragma unroll
                    for (int r = 0; r < RPT; r++) {
                        acc[r][2*j + 0] = f2_fma(q.x, pp[r], acc[r][2*j + 0]);
                        acc[r][2*j + 1] = f2_fma(q.y, pp[r], acc[r][2*j + 1]);
                    }
                }
            }
        }
        #pragma unroll
        for (int r = 0; r < RPT; r++)
            #pragma unroll
            for (int i = 0; i < 8; i++)
                f2_unpack(acc[r][i], ris[r][2*i], ris[r][2*i+1]);
    }

    // ---- output projection: out[c] = Σ_a U_output[a,c] ris[a] ----
    #pragma unroll
    for (int r = 0; r < RPT; r++) {
        if (!active[r]) continue;
        float o[16];
        #pragma unroll
        for (int c = 0; c < 16; c++) o[c] = 0.f;
        #pragma unroll
        for (int a = 0; a < 16; a++) {
            float ra = ris[r][a];
            #pragma unroll
            for (int c = 0; c < 16; c++)
                o[c] = fmaf(sUo[a * 16 + c], ra, o[c]);
        }
        float4* op = reinterpret_cast<float4*>(out + (size_t)rown[r] * 16);
        #pragma unroll
        for (int g = 0; g < 4; g++)
            op[g] = make_float4(o[4*g+0], o[4*g+1], o[4*g+2], o[4*g+3]);
    }
}

extern "C" void kernel_launch(void* const* d_in, const int* in_sizes, int n_in,
                              void* d_out, int out_size)
{
    const float* ns = (const float*)d_in[0];
    const float* U0 = (const float*)d_in[1];
    const float* Ur = (const float*)d_in[2];
    const float* Uo = (const float*)d_in[3];
    float* out = (float*)d_out;

    cudaFuncSetAttribute(tt_agg_kernel,
                         cudaFuncAttributeMaxDynamicSharedMemorySize, SMEM_BYTES);

    int grid = (NROWS + ROWS_PER_BLK - 1) / ROWS_PER_BLK;
    tt_agg_kernel<<<grid, TPB, SMEM_BYTES>>>(ns, U0, Ur, Uo, out);
}

// round 5
// speedup vs baseline: 2.2611x; 1.7983x over previous
#include <cuda_runtime.h>
#include <cuda_bf16.h>
#include <cstdint>

// ============================================================================
// TTAggregator via mma.sync.m16n8k16 bf16 (base ISA — harness ptxas targets
// sm_103 without the "a" suffix, so tcgen05 is unavailable).
//
// Per step d: ris_new[n,c] = sum_{a,b} U_d[a,b,c]*ris[n,a]*h_d[n,b]
//   k = a*16+b (K=256, 16 k-tiles; k-tile kt <=> a = kt)
//   A (16x16 per kt, row-major) : A[c][b] = U_d[kt][b][c]      (shared!)
//   B (16x8  per kt, col-major) : B[b][n] = ris[n][kt]*h[n][b] (per-row)
//   D (16x8)                    : D[c][n] accumulated fp32 over kt
// Split precision (fp32 = hi + lo, hi = top-16-bit truncation, exact in bf16):
//   D = Uhi*Zhi + Ulo*Zhi + Uhi*Zlo   (3 passes; lo*lo term ~2^-17 dropped)
// ============================================================================

static constexpr int NROWS  = 1000000;
static constexpr int DEG    = 10;
static constexpr int TPB    = 256;          // 8 warps
static constexpr int NTILES = 4;            // 8-row tiles per warp -> 32 rows/warp
static constexpr int ROWS_PER_CTA = TPB;    // 256

static constexpr int RIS_STRIDE = 20;       // floats/row: pad -> conflict-free + 16B aligned

// smem layout (bytes):
//   ufrag: [d(9)][pass(2)][kt(16)][lane(32)] x uint4  = 147456
//   sris : 256 rows x 20 f32                          =  20480
//   sUo, sU0 : 1KB each
static constexpr int SM_UFRAG = 0;
static constexpr int SM_RIS   = 9 * 2 * 16 * 512;            // 147456
static constexpr int SM_UO    = SM_RIS + ROWS_PER_CTA * RIS_STRIDE * 4;
static constexpr int SM_U0    = SM_UO + 1024;
static constexpr int SMEM_BYTES = SM_U0 + 1024;              // 169984

// ---- packing helpers ----
// pack two fp32 -> bf16x2 by TRUNCATION (the "hi" parts; low half = first elem)
__device__ __forceinline__ uint32_t pack_hi(float x, float y) {
    uint32_t r;
    asm("prmt.b32 %0, %1, %2, 0x7632;"
        : "=r"(r) : "r"(__float_as_uint(x)), "r"(__float_as_uint(y)));
    return r;
}
// residuals (x - hi(x)) rounded to bf16x2 given the packed hi bits
__device__ __forceinline__ uint32_t pack_lo(float x, float y, uint32_t hibits) {
    float hx = __uint_as_float(hibits << 16);
    float hy = __uint_as_float(hibits & 0xffff0000u);
    float lx = x - hx;          // exact (Dekker-style split)
    float ly = y - hy;
    uint32_t r;
    asm("cvt.rn.bf16x2.f32 %0, %1, %2;" : "=r"(r) : "f"(ly), "f"(lx));
    return r;
}
// residual pack directly from fp32 (for U-fragment build)
__device__ __forceinline__ uint32_t pack_lo_direct(float x, float y) {
    float hx = __uint_as_float(__float_as_uint(x) & 0xffff0000u);
    float hy = __uint_as_float(__float_as_uint(y) & 0xffff0000u);
    float lx = x - hx, ly = y - hy;
    uint32_t r;
    asm("cvt.rn.bf16x2.f32 %0, %1, %2;" : "=r"(r) : "f"(ly), "f"(lx));
    return r;
}

struct F4 { float x, y, z, w; };

__device__ __forceinline__ void mma16816(F4& d, const uint4& a, uint32_t b0, uint32_t b1) {
    asm volatile(
        "mma.sync.aligned.m16n8k16.row.col.f32.bf16.bf16.f32 "
        "{%0,%1,%2,%3}, {%4,%5,%6,%7}, {%8,%9}, {%0,%1,%2,%3};"
        : "+f"(d.x), "+f"(d.y), "+f"(d.z), "+f"(d.w)
        : "r"(a.x), "r"(a.y), "r"(a.z), "r"(a.w), "r"(b0), "r"(b1));
}

__global__ __launch_bounds__(TPB, 1)
void tt_mma_kernel(const float* __restrict__ ns,
                   const float* __restrict__ U0,
                   const float* __restrict__ Ur,
                   const float* __restrict__ Uo,
                   float* __restrict__ out)
{
    extern __shared__ char smem[];
    uint32_t* ufrag = (uint32_t*)(smem + SM_UFRAG);
    float*    sris  = (float*)(smem + SM_RIS);
    float*    sUo   = (float*)(smem + SM_UO);
    float*    sU0   = (float*)(smem + SM_U0);

    const int tid  = threadIdx.x;
    const int lane = tid & 31;
    const int w    = tid >> 5;
    const int m    = lane & 3;      // threadID_in_group
    const int g    = lane >> 2;     // groupID
    const long long cta_row0 = (long long)blockIdx.x * ROWS_PER_CTA;

    // ---- build U hi/lo A-fragments in exact mma fragment order ----
    // slot i -> (d, kt, lane'):  A[c][b] = U_d[kt][b][c]
    for (int i = tid; i < 9 * 16 * 32; i += TPB) {
        int d  = i >> 9;
        int kt = (i >> 5) & 15;
        int ln = i & 31;
        int lm = ln & 3, lg = ln >> 2;
        const float* Ua = Ur + d * 4096 + kt * 256;   // [b][c]
        float u00 = Ua[(2*lm    )*16 + lg    ], u01 = Ua[(2*lm + 1)*16 + lg    ];
        float u10 = Ua[(2*lm    )*16 + lg + 8], u11 = Ua[(2*lm + 1)*16 + lg + 8];
        float u20 = Ua[(2*lm + 8)*16 + lg    ], u21 = Ua[(2*lm + 9)*16 + lg    ];
        float u30 = Ua[(2*lm + 8)*16 + lg + 8], u31 = Ua[(2*lm + 9)*16 + lg + 8];
        uint4 hi = make_uint4(pack_hi(u00,u01), pack_hi(u10,u11),
                              pack_hi(u20,u21), pack_hi(u30,u31));
        uint4 lo = make_uint4(pack_lo_direct(u00,u01), pack_lo_direct(u10,u11),
                              pack_lo_direct(u20,u21), pack_lo_direct(u30,u31));
        *(uint4*)&ufrag[((d*2 + 0)*16 + kt)*128 + ln*4] = hi;
        *(uint4*)&ufrag[((d*2 + 1)*16 + kt)*128 + ln*4] = lo;
    }
    for (int i = tid; i < 256; i += TPB) { sU0[i] = U0[i]; sUo[i] = Uo[i]; }
    __syncthreads();

    // ---- ris0 = U0^T h0, one thread per row ----
    {
        long long r = cta_row0 + tid; if (r > NROWS - 1) r = NROWS - 1;
        const float* p = ns + (size_t)r * (DEG * 16);
        float h0[16];
        #pragma unroll
        for (int q = 0; q < 4; q++) {
            float4 v = *(const float4*)(p + q * 4);
            h0[4*q] = v.x; h0[4*q+1] = v.y; h0[4*q+2] = v.z; h0[4*q+3] = v.w;
        }
        float acc[16];
        #pragma unroll
        for (int c = 0; c < 16; c++) acc[c] = 0.f;
        #pragma unroll
        for (int b = 0; b < 16; b++) {
            float hb = h0[b];
            #pragma unroll
            for (int c = 0; c < 16; c++) acc[c] = fmaf(sU0[b*16 + c], hb, acc[c]);
        }
        #pragma unroll
        for (int c = 0; c < 16; c++) sris[tid * RIS_STRIDE + c] = acc[c];
    }
    __syncwarp();

    // ================= main loop: 9 TT steps, warps independent =============
    #pragma unroll 1
    for (int d = 1; d < DEG; d++) {
        // U fragments resident in registers for the whole step
        const uint32_t* fh = &ufrag[((d-1)*2 + 0) * 2048];
        const uint32_t* fl = &ufrag[((d-1)*2 + 1) * 2048];
        uint4 uh[16], ul[16];
        #pragma unroll
        for (int kt = 0; kt < 16; kt++) {
            uh[kt] = *(const uint4*)&fh[kt*128 + lane*4];
            ul[kt] = *(const uint4*)&fl[kt*128 + lane*4];
        }
        // prefetch this step's h values for all 4 tiles (MLP=8)
        float2 ha[NTILES], hb[NTILES];
        #pragma unroll
        for (int T = 0; T < NTILES; T++) {
            long long r = cta_row0 + w*32 + T*8 + g; if (r > NROWS - 1) r = NROWS - 1;
            const float* p = ns + (size_t)r * (DEG * 16) + d * 16 + 2 * m;
            ha[T] = *(const float2*)p;
            hb[T] = *(const float2*)(p + 8);
        }

        #pragma unroll 1
        for (int T = 0; T < NTILES; T++) {
            const int rowbase = w*32 + T*8;
            // my row's ris (row index n = g within the tile)
            const float4* rp = (const float4*)&sris[(rowbase + g) * RIS_STRIDE];
            float4 q0 = rp[0], q1 = rp[1], q2 = rp[2], q3 = rp[3];
            float r16[16] = { q0.x,q0.y,q0.z,q0.w, q1.x,q1.y,q1.z,q1.w,
                              q2.x,q2.y,q2.z,q2.w, q3.x,q3.y,q3.z,q3.w };
            __syncwarp();   // all lanes read old ris before anyone overwrites

            // Z hi fragments: B[b][n=g] = ris[g][kt] * h[g][b]
            uint32_t zb0[16], zb1[16];
            #pragma unroll
            for (int kt = 0; kt < 16; kt++) {
                float z0 = r16[kt]*ha[T].x, z1 = r16[kt]*ha[T].y;
                float z2 = r16[kt]*hb[T].x, z3 = r16[kt]*hb[T].y;
                zb0[kt] = pack_hi(z0, z1);
                zb1[kt] = pack_hi(z2, z3);
            }
            F4 dE = {0,0,0,0}, dO = {0,0,0,0};   // even/odd kt accum (chain split)
            #pragma unroll
            for (int kt = 0; kt < 16; kt++)
                mma16816((kt & 1) ? dO : dE, uh[kt], zb0[kt], zb1[kt]);
            #pragma unroll
            for (int kt = 0; kt < 16; kt++)
                mma16816((kt & 1) ? dO : dE, ul[kt], zb0[kt], zb1[kt]);
            // Z lo fragments (recompute z, subtract hi, overwrite zb)
            #pragma unroll
            for (int kt = 0; kt < 16; kt++) {
                float z0 = r16[kt]*ha[T].x, z1 = r16[kt]*ha[T].y;
                float z2 = r16[kt]*hb[T].x, z3 = r16[kt]*hb[T].y;
                zb0[kt] = pack_lo(z0, z1, zb0[kt]);
                zb1[kt] = pack_lo(z2, z3, zb1[kt]);
            }
            #pragma unroll
            for (int kt = 0; kt < 16; kt++)
                mma16816((kt & 1) ? dO : dE, uh[kt], zb0[kt], zb1[kt]);

            // D frag: lane holds channels {g, g+8} of rows {2m, 2m+1}
            const int r0w = rowbase + 2*m, r1w = r0w + 1;
            sris[r0w*RIS_STRIDE + g    ] = dE.x + dO.x;
            sris[r1w*RIS_STRIDE + g    ] = dE.y + dO.y;
            sris[r0w*RIS_STRIDE + g + 8] = dE.z + dO.z;
            sris[r1w*RIS_STRIDE + g + 8] = dE.w + dO.w;
            __syncwarp();
        }
    }

    // ---- output projection: out[c] = sum_a Uo[a,c] * ris[a] ----
    const long long orow = cta_row0 + tid;
    if (orow < NROWS) {
        const float4* rp = (const float4*)&sris[tid * RIS_STRIDE];
        float4 q0 = rp[0], q1 = rp[1], q2 = rp[2], q3 = rp[3];
        float rv[16] = { q0.x,q0.y,q0.z,q0.w, q1.x,q1.y,q1.z,q1.w,
                         q2.x,q2.y,q2.z,q2.w, q3.x,q3.y,q3.z,q3.w };
        float o[16];
        #pragma unroll
        for (int c = 0; c < 16; c++) o[c] = 0.f;
        #pragma unroll
        for (int a = 0; a < 16; a++) {
            float ra = rv[a];
            #pragma unroll
            for (int c = 0; c < 16; c++) o[c] = fmaf(sUo[a*16 + c], ra, o[c]);
        }
        float4* op = (float4*)(out + (size_t)orow * 16);
        #pragma unroll
        for (int q = 0; q < 4; q++)
            op[q] = make_float4(o[4*q], o[4*q+1], o[4*q+2], o[4*q+3]);
    }
}

extern "C" void kernel_launch(void* const* d_in, const int* in_sizes, int n_in,
                              void* d_out, int out_size)
{
    const float* ns = (const float*)d_in[0];
    const float* U0 = (const float*)d_in[1];
    const float* Ur = (const float*)d_in[2];
    const float* Uo = (const float*)d_in[3];
    float* out = (float*)d_out;

    cudaFuncSetAttribute(tt_mma_kernel,
                         cudaFuncAttributeMaxDynamicSharedMemorySize, SMEM_BYTES);

    int grid = (NROWS + ROWS_PER_CTA - 1) / ROWS_PER_CTA;
    tt_mma_kernel<<<grid, TPB, SMEM_BYTES>>>(ns, U0, Ur, Uo, out);
}

// round 6
// speedup vs baseline: 2.2832x; 1.0098x over previous
#include <cuda_runtime.h>
#include <cuda_bf16.h>
#include <cstdint>

// ============================================================================
// TTAggregator via mma.sync.m16n8k16 bf16 (base-ISA HMMA; ptxas targets sm_103
// so tcgen05 is unavailable).
//
// Per step d: ris_new[n,c] = sum_{a,b} U_d[a,b,c]*ris[n,a]*h_d[n,b]
//   k = a*16+b (K=256, 16 k-tiles; k-tile kt <=> a = kt)
//   A (16x16 per kt, row-major) : A[c][b] = U_d[kt][b][c]      (shared!)
//   B (16x8  per kt, col-major) : B[b][n] = ris[n][kt]*h[n][b] (per-row)
// Split precision (fp32 = hi + lo, hi = top-16-bit truncation, exact in bf16):
//   D = Uhi*Zhi + Ulo*Zhi + Uhi*Zlo   (3 contributions; lo*lo ~2^-17 dropped)
// R6: single kt-sweep issuing all 3 contributions per kt into 6 independent
// accumulator chains (pass x even/odd kt) -> HMMA RAW latency fully hidden.
// ============================================================================

static constexpr int NROWS  = 1000000;
static constexpr int DEG    = 10;
static constexpr int TPB    = 256;          // 8 warps
static constexpr int NTILES = 4;            // 8-row tiles per warp -> 32 rows/warp
static constexpr int ROWS_PER_CTA = TPB;    // 256

static constexpr int RIS_STRIDE = 20;       // floats/row: conflict-free + 16B aligned

// smem layout (bytes):
//   ufrag: [d(9)][pass(2)][kt(16)][lane(32)] x uint4  = 147456
//   sris : 256 rows x 20 f32                          =  20480
//   sUo, sU0 : 1KB each
static constexpr int SM_UFRAG = 0;
static constexpr int SM_RIS   = 9 * 2 * 16 * 512;            // 147456
static constexpr int SM_UO    = SM_RIS + ROWS_PER_CTA * RIS_STRIDE * 4;
static constexpr int SM_U0    = SM_UO + 1024;
static constexpr int SMEM_BYTES = SM_U0 + 1024;              // 169984

// ---- packing helpers ----
__device__ __forceinline__ uint32_t pack_hi(float x, float y) {
    uint32_t r;
    asm("prmt.b32 %0, %1, %2, 0x7632;"
        : "=r"(r) : "r"(__float_as_uint(x)), "r"(__float_as_uint(y)));
    return r;
}
__device__ __forceinline__ uint32_t pack_lo(float x, float y, uint32_t hibits) {
    float hx = __uint_as_float(hibits << 16);
    float hy = __uint_as_float(hibits & 0xffff0000u);
    float lx = x - hx;          // exact (Dekker-style split)
    float ly = y - hy;
    uint32_t r;
    asm("cvt.rn.bf16x2.f32 %0, %1, %2;" : "=r"(r) : "f"(ly), "f"(lx));
    return r;
}
__device__ __forceinline__ uint32_t pack_lo_direct(float x, float y) {
    float hx = __uint_as_float(__float_as_uint(x) & 0xffff0000u);
    float hy = __uint_as_float(__float_as_uint(y) & 0xffff0000u);
    float lx = x - hx, ly = y - hy;
    uint32_t r;
    asm("cvt.rn.bf16x2.f32 %0, %1, %2;" : "=r"(r) : "f"(ly), "f"(lx));
    return r;
}

struct F4 { float x, y, z, w; };

__device__ __forceinline__ void mma16816(F4& d, const uint4& a, uint32_t b0, uint32_t b1) {
    asm volatile(
        "mma.sync.aligned.m16n8k16.row.col.f32.bf16.bf16.f32 "
        "{%0,%1,%2,%3}, {%4,%5,%6,%7}, {%8,%9}, {%0,%1,%2,%3};"
        : "+f"(d.x), "+f"(d.y), "+f"(d.z), "+f"(d.w)
        : "r"(a.x), "r"(a.y), "r"(a.z), "r"(a.w), "r"(b0), "r"(b1));
}

__global__ __launch_bounds__(TPB, 1)
void tt_mma_kernel(const float* __restrict__ ns,
                   const float* __restrict__ U0,
                   const float* __restrict__ Ur,
                   const float* __restrict__ Uo,
                   float* __restrict__ out)
{
    extern __shared__ char smem[];
    uint32_t* ufrag = (uint32_t*)(smem + SM_UFRAG);
    float*    sris  = (float*)(smem + SM_RIS);
    float*    sUo   = (float*)(smem + SM_UO);
    float*    sU0   = (float*)(smem + SM_U0);

    const int tid  = threadIdx.x;
    const int lane = tid & 31;
    const int w    = tid >> 5;
    const int m    = lane & 3;      // threadID_in_group
    const int g    = lane >> 2;     // groupID
    const long long cta_row0 = (long long)blockIdx.x * ROWS_PER_CTA;

    // ---- build U hi/lo A-fragments in exact mma fragment order ----
    for (int i = tid; i < 9 * 16 * 32; i += TPB) {
        int d  = i >> 9;
        int kt = (i >> 5) & 15;
        int ln = i & 31;
        int lm = ln & 3, lg = ln >> 2;
        const float* Ua = Ur + d * 4096 + kt * 256;   // [b][c]
        float u00 = Ua[(2*lm    )*16 + lg    ], u01 = Ua[(2*lm + 1)*16 + lg    ];
        float u10 = Ua[(2*lm    )*16 + lg + 8], u11 = Ua[(2*lm + 1)*16 + lg + 8];
        float u20 = Ua[(2*lm + 8)*16 + lg    ], u21 = Ua[(2*lm + 9)*16 + lg    ];
        float u30 = Ua[(2*lm + 8)*16 + lg + 8], u31 = Ua[(2*lm + 9)*16 + lg + 8];
        uint4 hi = make_uint4(pack_hi(u00,u01), pack_hi(u10,u11),
                              pack_hi(u20,u21), pack_hi(u30,u31));
        uint4 lo = make_uint4(pack_lo_direct(u00,u01), pack_lo_direct(u10,u11),
                              pack_lo_direct(u20,u21), pack_lo_direct(u30,u31));
        *(uint4*)&ufrag[((d*2 + 0)*16 + kt)*128 + ln*4] = hi;
        *(uint4*)&ufrag[((d*2 + 1)*16 + kt)*128 + ln*4] = lo;
    }
    for (int i = tid; i < 256; i += TPB) { sU0[i] = U0[i]; sUo[i] = Uo[i]; }
    __syncthreads();

    // ---- ris0 = U0^T h0, one thread per row ----
    {
        long long r = cta_row0 + tid; if (r > NROWS - 1) r = NROWS - 1;
        const float* p = ns + (size_t)r * (DEG * 16);
        float h0[16];
        #pragma unroll
        for (int q = 0; q < 4; q++) {
            float4 v = *(const float4*)(p + q * 4);
            h0[4*q] = v.x; h0[4*q+1] = v.y; h0[4*q+2] = v.z; h0[4*q+3] = v.w;
        }
        float acc[16];
        #pragma unroll
        for (int c = 0; c < 16; c++) acc[c] = 0.f;
        #pragma unroll
        for (int b = 0; b < 16; b++) {
            float hb = h0[b];
            #pragma unroll
            for (int c = 0; c < 16; c++) acc[c] = fmaf(sU0[b*16 + c], hb, acc[c]);
        }
        #pragma unroll
        for (int c = 0; c < 16; c++) sris[tid * RIS_STRIDE + c] = acc[c];
    }
    __syncwarp();

    // ================= main loop: 9 TT steps, warps independent =============
    #pragma unroll 1
    for (int d = 1; d < DEG; d++) {
        // U fragments resident in registers for the whole step
        const uint32_t* fh = &ufrag[((d-1)*2 + 0) * 2048];
        const uint32_t* fl = &ufrag[((d-1)*2 + 1) * 2048];
        uint4 uh[16], ul[16];
        #pragma unroll
        for (int kt = 0; kt < 16; kt++) {
            uh[kt] = *(const uint4*)&fh[kt*128 + lane*4];
            ul[kt] = *(const uint4*)&fl[kt*128 + lane*4];
        }
        // prefetch this step's h values for all 4 tiles (MLP=8)
        float2 ha[NTILES], hb[NTILES];
        #pragma unroll
        for (int T = 0; T < NTILES; T++) {
            long long r = cta_row0 + w*32 + T*8 + g; if (r > NROWS - 1) r = NROWS - 1;
            const float* p = ns + (size_t)r * (DEG * 16) + d * 16 + 2 * m;
            ha[T] = *(const float2*)p;
            hb[T] = *(const float2*)(p + 8);
        }

        #pragma unroll 1
        for (int T = 0; T < NTILES; T++) {
            const int rowbase = w*32 + T*8;
            // my row's ris (row index n = g within the tile)
            const float4* rp = (const float4*)&sris[(rowbase + g) * RIS_STRIDE];
            float4 q0 = rp[0], q1 = rp[1], q2 = rp[2], q3 = rp[3];
            float r16[16] = { q0.x,q0.y,q0.z,q0.w, q1.x,q1.y,q1.z,q1.w,
                              q2.x,q2.y,q2.z,q2.w, q3.x,q3.y,q3.z,q3.w };
            __syncwarp();   // all lanes read old ris before anyone overwrites

            // 6 independent accumulator chains: pass{UhiZhi,UloZhi,UhiZlo} x {even,odd kt}
            F4 acc[6];
            #pragma unroll
            for (int i = 0; i < 6; i++) acc[i] = F4{0,0,0,0};

            #pragma unroll
            for (int kt = 0; kt < 16; kt++) {
                const int par = (kt & 1) * 3;
                float z0 = r16[kt]*ha[T].x, z1 = r16[kt]*ha[T].y;
                float z2 = r16[kt]*hb[T].x, z3 = r16[kt]*hb[T].y;
                uint32_t zh0 = pack_hi(z0, z1);
                uint32_t zh1 = pack_hi(z2, z3);
                mma16816(acc[par + 0], uh[kt], zh0, zh1);
                mma16816(acc[par + 1], ul[kt], zh0, zh1);
                uint32_t zl0 = pack_lo(z0, z1, zh0);
                uint32_t zl1 = pack_lo(z2, z3, zh1);
                mma16816(acc[par + 2], uh[kt], zl0, zl1);
            }

            // D frag: lane holds channels {g, g+8} of rows {2m, 2m+1}
            const int r0w = rowbase + 2*m, r1w = r0w + 1;
            sris[r0w*RIS_STRIDE + g    ] = ((acc[0].x + acc[3].x) + (acc[1].x + acc[4].x)) + (acc[2].x + acc[5].x);
            sris[r1w*RIS_STRIDE + g    ] = ((acc[0].y + acc[3].y) + (acc[1].y + acc[4].y)) + (acc[2].y + acc[5].y);
            sris[r0w*RIS_STRIDE + g + 8] = ((acc[0].z + acc[3].z) + (acc[1].z + acc[4].z)) + (acc[2].z + acc[5].z);
            sris[r1w*RIS_STRIDE + g + 8] = ((acc[0].w + acc[3].w) + (acc[1].w + acc[4].w)) + (acc[2].w + acc[5].w);
            __syncwarp();
        }
    }

    // ---- output projection: out[c] = sum_a Uo[a,c] * ris[a] ----
    const long long orow = cta_row0 + tid;
    if (orow < NROWS) {
        const float4* rp = (const float4*)&sris[tid * RIS_STRIDE];
        float4 q0 = rp[0], q1 = rp[1], q2 = rp[2], q3 = rp[3];
        float rv[16] = { q0.x,q0.y,q0.z,q0.w, q1.x,q1.y,q1.z,q1.w,
                         q2.x,q2.y,q2.z,q2.w, q3.x,q3.y,q3.z,q3.w };
        float o[16];
        #pragma unroll
        for (int c = 0; c < 16; c++) o[c] = 0.f;
        #pragma unroll
        for (int a = 0; a < 16; a++) {
            float ra = rv[a];
            #pragma unroll
            for (int c = 0; c < 16; c++) o[c] = fmaf(sUo[a*16 + c], ra, o[c]);
        }
        float4* op = (float4*)(out + (size_t)orow * 16);
        #pragma unroll
        for (int q = 0; q < 4; q++)
            op[q] = make_float4(o[4*q], o[4*q+1], o[4*q+2], o[4*q+3]);
    }
}

extern "C" void kernel_launch(void* const* d_in, const int* in_sizes, int n_in,
                              void* d_out, int out_size)
{
    const float* ns = (const float*)d_in[0];
    const float* U0 = (const float*)d_in[1];
    const float* Ur = (const float*)d_in[2];
    const float* Uo = (const float*)d_in[3];
    float* out = (float*)d_out;

    cudaFuncSetAttribute(tt_mma_kernel,
                         cudaFuncAttributeMaxDynamicSharedMemorySize, SMEM_BYTES);

    int grid = (NROWS + ROWS_PER_CTA - 1) / ROWS_PER_CTA;
    tt_mma_kernel<<<grid, TPB, SMEM_BYTES>>>(ns, U0, Ur, Uo, out);
}

// round 7
// speedup vs baseline: 2.2843x; 1.0005x over previous
#include <cuda_runtime.h>
#include <cuda_bf16.h>
#include <cstdint>

// ============================================================================
// TTAggregator via mma.sync.m16n8k16 bf16 (base-ISA HMMA; ptxas targets sm_103
// so tcgen05 is unavailable).
//
// Per step d: ris_new[n,c] = sum_{a,b} U_d[a,b,c]*ris[n,a]*h_d[n,b]
//   k = a*16+b (K=256, 16 k-tiles; k-tile kt <=> a = kt)
//   A (16x16 per kt, row-major) : A[c][b] = U_d[kt][b][c]      (shared!)
//   B (16x8  per kt, col-major) : B[b][n] = ris[n][kt]*h[n][b] (per-row)
// Split precision (fp32 = hi + lo, hi = top-16-bit truncation, exact in bf16):
//   D = Uhi*Zhi + Ulo*Zhi + Uhi*Zlo   (3 contributions; lo*lo ~2^-17 dropped)
// R6: single kt-sweep issuing all 3 contributions per kt into 6 independent
// accumulator chains (pass x even/odd kt) -> HMMA RAW latency fully hidden.
// ============================================================================

static constexpr int NROWS  = 1000000;
static constexpr int DEG    = 10;
static constexpr int TPB    = 256;          // 8 warps
static constexpr int NTILES = 4;            // 8-row tiles per warp -> 32 rows/warp
static constexpr int ROWS_PER_CTA = TPB;    // 256

static constexpr int RIS_STRIDE = 20;       // floats/row: conflict-free + 16B aligned

// smem layout (bytes):
//   ufrag: [d(9)][pass(2)][kt(16)][lane(32)] x uint4  = 147456
//   sris : 256 rows x 20 f32                          =  20480
//   sUo, sU0 : 1KB each
static constexpr int SM_UFRAG = 0;
static constexpr int SM_RIS   = 9 * 2 * 16 * 512;            // 147456
static constexpr int SM_UO    = SM_RIS + ROWS_PER_CTA * RIS_STRIDE * 4;
static constexpr int SM_U0    = SM_UO + 1024;
static constexpr int SMEM_BYTES = SM_U0 + 1024;              // 169984

// ---- packing helpers ----
__device__ __forceinline__ uint32_t pack_hi(float x, float y) {
    uint32_t r;
    asm("prmt.b32 %0, %1, %2, 0x7632;"
        : "=r"(r) : "r"(__float_as_uint(x)), "r"(__float_as_uint(y)));
    return r;
}
__device__ __forceinline__ uint32_t pack_lo(float x, float y, uint32_t hibits) {
    float hx = __uint_as_float(hibits << 16);
    float hy = __uint_as_float(hibits & 0xffff0000u);
    float lx = x - hx;          // exact (Dekker-style split)
    float ly = y - hy;
    uint32_t r;
    asm("cvt.rn.bf16x2.f32 %0, %1, %2;" : "=r"(r) : "f"(ly), "f"(lx));
    return r;
}
__device__ __forceinline__ uint32_t pack_lo_direct(float x, float y) {
    float hx = __uint_as_float(__float_as_uint(x) & 0xffff0000u);
    float hy = __uint_as_float(__float_as_uint(y) & 0xffff0000u);
    float lx = x - hx, ly = y - hy;
    uint32_t r;
    asm("cvt.rn.bf16x2.f32 %0, %1, %2;" : "=r"(r) : "f"(ly), "f"(lx));
    return r;
}

struct F4 { float x, y, z, w; };

__device__ __forceinline__ void mma16816(F4& d, const uint4& a, uint32_t b0, uint32_t b1) {
    asm volatile(
        "mma.sync.aligned.m16n8k16.row.col.f32.bf16.bf16.f32 "
        "{%0,%1,%2,%3}, {%4,%5,%6,%7}, {%8,%9}, {%0,%1,%2,%3};"
        : "+f"(d.x), "+f"(d.y), "+f"(d.z), "+f"(d.w)
        : "r"(a.x), "r"(a.y), "r"(a.z), "r"(a.w), "r"(b0), "r"(b1));
}

__global__ __launch_bounds__(TPB, 1)
void tt_mma_kernel(const float* __restrict__ ns,
                   const float* __restrict__ U0,
                   const float* __restrict__ Ur,
                   const float* __restrict__ Uo,
                   float* __restrict__ out)
{
    extern __shared__ char smem[];
    uint32_t* ufrag = (uint32_t*)(smem + SM_UFRAG);
    float*    sris  = (float*)(smem + SM_RIS);
    float*    sUo   = (float*)(smem + SM_UO);
    float*    sU0   = (float*)(smem + SM_U0);

    const int tid  = threadIdx.x;
    const int lane = tid & 31;
    const int w    = tid >> 5;
    const int m    = lane & 3;      // threadID_in_group
    const int g    = lane >> 2;     // groupID
    const long long cta_row0 = (long long)blockIdx.x * ROWS_PER_CTA;

    // ---- build U hi/lo A-fragments in exact mma fragment order ----
    for (int i = tid; i < 9 * 16 * 32; i += TPB) {
        int d  = i >> 9;
        int kt = (i >> 5) & 15;
        int ln = i & 31;
        int lm = ln & 3, lg = ln >> 2;
        const float* Ua = Ur + d * 4096 + kt * 256;   // [b][c]
        float u00 = Ua[(2*lm    )*16 + lg    ], u01 = Ua[(2*lm + 1)*16 + lg    ];
        float u10 = Ua[(2*lm    )*16 + lg + 8], u11 = Ua[(2*lm + 1)*16 + lg + 8];
        float u20 = Ua[(2*lm + 8)*16 + lg    ], u21 = Ua[(2*lm + 9)*16 + lg    ];
        float u30 = Ua[(2*lm + 8)*16 + lg + 8], u31 = Ua[(2*lm + 9)*16 + lg + 8];
        uint4 hi = make_uint4(pack_hi(u00,u01), pack_hi(u10,u11),
                              pack_hi(u20,u21), pack_hi(u30,u31));
        uint4 lo = make_uint4(pack_lo_direct(u00,u01), pack_lo_direct(u10,u11),
                              pack_lo_direct(u20,u21), pack_lo_direct(u30,u31));
        *(uint4*)&ufrag[((d*2 + 0)*16 + kt)*128 + ln*4] = hi;
        *(uint4*)&ufrag[((d*2 + 1)*16 + kt)*128 + ln*4] = lo;
    }
    for (int i = tid; i < 256; i += TPB) { sU0[i] = U0[i]; sUo[i] = Uo[i]; }
    __syncthreads();

    // ---- ris0 = U0^T h0, one thread per row ----
    {
        long long r = cta_row0 + tid; if (r > NROWS - 1) r = NROWS - 1;
        const float* p = ns + (size_t)r * (DEG * 16);
        float h0[16];
        #pragma unroll
        for (int q = 0; q < 4; q++) {
            float4 v = *(const float4*)(p + q * 4);
            h0[4*q] = v.x; h0[4*q+1] = v.y; h0[4*q+2] = v.z; h0[4*q+3] = v.w;
        }
        float acc[16];
        #pragma unroll
        for (int c = 0; c < 16; c++) acc[c] = 0.f;
        #pragma unroll
        for (int b = 0; b < 16; b++) {
            float hb = h0[b];
            #pragma unroll
            for (int c = 0; c < 16; c++) acc[c] = fmaf(sU0[b*16 + c], hb, acc[c]);
        }
        #pragma unroll
        for (int c = 0; c < 16; c++) sris[tid * RIS_STRIDE + c] = acc[c];
    }
    __syncwarp();

    // ================= main loop: 9 TT steps, warps independent =============
    #pragma unroll 1
    for (int d = 1; d < DEG; d++) {
        // U fragments resident in registers for the whole step
        const uint32_t* fh = &ufrag[((d-1)*2 + 0) * 2048];
        const uint32_t* fl = &ufrag[((d-1)*2 + 1) * 2048];
        uint4 uh[16], ul[16];
        #pragma unroll
        for (int kt = 0; kt < 16; kt++) {
            uh[kt] = *(const uint4*)&fh[kt*128 + lane*4];
            ul[kt] = *(const uint4*)&fl[kt*128 + lane*4];
        }
        // prefetch this step's h values for all 4 tiles (MLP=8)
        float2 ha[NTILES], hb[NTILES];
        #pragma unroll
        for (int T = 0; T < NTILES; T++) {
            long long r = cta_row0 + w*32 + T*8 + g; if (r > NROWS - 1) r = NROWS - 1;
            const float* p = ns + (size_t)r * (DEG * 16) + d * 16 + 2 * m;
            ha[T] = *(const float2*)p;
            hb[T] = *(const float2*)(p + 8);
        }

        #pragma unroll 1
        for (int T = 0; T < NTILES; T++) {
            const int rowbase = w*32 + T*8;
            // my row's ris (row index n = g within the tile)
            const float4* rp = (const float4*)&sris[(rowbase + g) * RIS_STRIDE];
            float4 q0 = rp[0], q1 = rp[1], q2 = rp[2], q3 = rp[3];
            float r16[16] = { q0.x,q0.y,q0.z,q0.w, q1.x,q1.y,q1.z,q1.w,
                              q2.x,q2.y,q2.z,q2.w, q3.x,q3.y,q3.z,q3.w };
            __syncwarp();   // all lanes read old ris before anyone overwrites

            // 6 independent accumulator chains: pass{UhiZhi,UloZhi,UhiZlo} x {even,odd kt}
            F4 acc[6];
            #pragma unroll
            for (int i = 0; i < 6; i++) acc[i] = F4{0,0,0,0};

            #pragma unroll
            for (int kt = 0; kt < 16; kt++) {
                const int par = (kt & 1) * 3;
                float z0 = r16[kt]*ha[T].x, z1 = r16[kt]*ha[T].y;
                float z2 = r16[kt]*hb[T].x, z3 = r16[kt]*hb[T].y;
                uint32_t zh0 = pack_hi(z0, z1);
                uint32_t zh1 = pack_hi(z2, z3);
                mma16816(acc[par + 0], uh[kt], zh0, zh1);
                mma16816(acc[par + 1], ul[kt], zh0, zh1);
                uint32_t zl0 = pack_lo(z0, z1, zh0);
                uint32_t zl1 = pack_lo(z2, z3, zh1);
                mma16816(acc[par + 2], uh[kt], zl0, zl1);
            }

            // D frag: lane holds channels {g, g+8} of rows {2m, 2m+1}
            const int r0w = rowbase + 2*m, r1w = r0w + 1;
            sris[r0w*RIS_STRIDE + g    ] = ((acc[0].x + acc[3].x) + (acc[1].x + acc[4].x)) + (acc[2].x + acc[5].x);
            sris[r1w*RIS_STRIDE + g    ] = ((acc[0].y + acc[3].y) + (acc[1].y + acc[4].y)) + (acc[2].y + acc[5].y);
            sris[r0w*RIS_STRIDE + g + 8] = ((acc[0].z + acc[3].z) + (acc[1].z + acc[4].z)) + (acc[2].z + acc[5].z);
            sris[r1w*RIS_STRIDE + g + 8] = ((acc[0].w + acc[3].w) + (acc[1].w + acc[4].w)) + (acc[2].w + acc[5].w);
            __syncwarp();
        }
    }

    // ---- output projection: out[c] = sum_a Uo[a,c] * ris[a] ----
    const long long orow = cta_row0 + tid;
    if (orow < NROWS) {
        const float4* rp = (const float4*)&sris[tid * RIS_STRIDE];
        float4 q0 = rp[0], q1 = rp[1], q2 = rp[2], q3 = rp[3];
        float rv[16] = { q0.x,q0.y,q0.z,q0.w, q1.x,q1.y,q1.z,q1.w,
                         q2.x,q2.y,q2.z,q2.w, q3.x,q3.y,q3.z,q3.w };
        float o[16];
        #pragma unroll
        for (int c = 0; c < 16; c++) o[c] = 0.f;
        #pragma unroll
        for (int a = 0; a < 16; a++) {
            float ra = rv[a];
            #pragma unroll
            for (int c = 0; c < 16; c++) o[c] = fmaf(sUo[a*16 + c], ra, o[c]);
        }
        float4* op = (float4*)(out + (size_t)orow * 16);
        #pragma unroll
        for (int q = 0; q < 4; q++)
            op[q] = make_float4(o[4*q], o[4*q+1], o[4*q+2], o[4*q+3]);
    }
}

extern "C" void kernel_launch(void* const* d_in, const int* in_sizes, int n_in,
                              void* d_out, int out_size)
{
    const float* ns = (const float*)d_in[0];
    const float* U0 = (const float*)d_in[1];
    const float* Ur = (const float*)d_in[2];
    const float* Uo = (const float*)d_in[3];
    float* out = (float*)d_out;

    cudaFuncSetAttribute(tt_mma_kernel,
                         cudaFuncAttributeMaxDynamicSharedMemorySize, SMEM_BYTES);

    int grid = (NROWS + ROWS_PER_CTA - 1) / ROWS_PER_CTA;
    tt_mma_kernel<<<grid, TPB, SMEM_BYTES>>>(ns, U0, Ur, Uo, out);
}